// round 16
// baseline (speedup 1.0000x reference)
#include <cuda_runtime.h>
#include <cstdint>

#define N_NODES 100000
#define N_EDGES 3200000
#define N_FEAT  24
#define FPAD    32                 // padded feature stride (128 bytes)
#define LAYERS  6
#define EDGE_CAP 4000000           // padded total <= E + 7N = 3.9M; >=24 slack for prefetch overread
#define BUILD_BLOCKS  148
#define BUILD_THREADS 1024
#define CHUNK 676                  // ceil(N_NODES / BUILD_BLOCKS)

// ---------------------------------------------------------------------------
// Scratch (allocation-free rule: __device__ globals).
// Padded CSR: each row's g_edge segment is padded to a multiple of 8. Pad
// slots are NEVER written; __device__ globals are zero-init, so pads are
// permanently (val=0, off=0) -> harmless gathers of row 0 scaled by 0.
// Deterministic layout -> replay-safe. Feature buffers padded to FPAD=32
// floats (128B) so rows are line-aligned; only bytes 0..95 are requested.
// ---------------------------------------------------------------------------
__device__ __align__(16) float  g_bufP[(size_t)N_NODES * FPAD];
__device__ __align__(16) float  g_bufQ[(size_t)N_NODES * FPAD];
__device__ __align__(16) float2 g_edge[EDGE_CAP];   // (val, col*128 bits)
__device__ int g_cnt[N_NODES];        // real row lengths (build only)
__device__ int g_rowptr[N_NODES + 1]; // PADDED exclusive prefix
__device__ int g_cursor[N_NODES];
__device__ int g_bsum[BUILD_BLOCKS];
__device__ int g_boff[BUILD_BLOCKS];
// Monotone: int32 inputs -> set to 1 every run (idempotent); int64 -> stays 0.
__device__ int g_flag = 0;
// Monotone ticket barrier counter; never reset -> replay-safe.
__device__ unsigned g_bar = 0;

// ---------------------------------------------------------------------------
// Software grid barrier (persistent build kernel; 148 blocks = wave 1).
// ---------------------------------------------------------------------------
__device__ __forceinline__ void grid_barrier() {
    __syncthreads();
    if (threadIdx.x == 0) {
        __threadfence();
        unsigned ticket = atomicAdd(&g_bar, 1u);
        unsigned target = (ticket / BUILD_BLOCKS + 1u) * BUILD_BLOCKS;
        unsigned v;
        do {
            asm volatile("ld.global.acquire.gpu.u32 %0, [%1];"
                         : "=r"(v) : "l"(&g_bar));
            if (v < target) __nanosleep(64);
        } while (v < target);
    }
    __syncthreads();
}

__device__ __forceinline__ int load_idx(const void* p, int e, int flag) {
    int v = (flag == 1) ? ((const int*)p)[e] : (int)((const long long*)p)[e];
    return min(max(v, 0), N_NODES - 1);   // fault guard
}

// ---------------------------------------------------------------------------
// Persistent single-launch CSR build + x copy-in:
//   phase 0: zero counts, dtype probe (JAX x64-off downcasts int64->int32;
//            odd int32 words all-zero iff buffer is int64), copy x -> bufP
//   phase 1: row histogram
//   phase 2: exclusive scan of counts padded to multiples of 8
//   phase 3: scatter (val, col*128) into row-sorted padded g_edge
// ---------------------------------------------------------------------------
__global__ void __launch_bounds__(BUILD_THREADS)
build_csr_kernel(const void* __restrict__ rptr,
                 const void* __restrict__ cptr,
                 const float* __restrict__ vals,
                 const float* __restrict__ x) {
    const int tid    = threadIdx.x;
    const int gid    = blockIdx.x * BUILD_THREADS + tid;
    const int stride = BUILD_BLOCKS * BUILD_THREADS;

    // --- phase 0 ---
    for (int i = gid; i < N_NODES; i += stride) g_cnt[i] = 0;
    const int* p32 = (const int*)rptr;
    for (int i = gid; i < N_EDGES / 2; i += stride)
        if (p32[2 * i + 1] != 0) g_flag = 1;
    for (int i = gid; i < N_NODES * N_FEAT; i += stride) {
        int r = i / N_FEAT, f = i - r * N_FEAT;
        g_bufP[r * FPAD + f] = x[i];
    }
    grid_barrier();

    const int flag = g_flag;

    // --- phase 1: histogram ---
    for (int e = gid; e < N_EDGES; e += stride)
        atomicAdd(&g_cnt[load_idx(rptr, e, flag)], 1);
    grid_barrier();

    // --- phase 2a: block-local exclusive scan of padded counts ---
    {
        __shared__ int s_w[32];
        int lane = tid & 31, wid = tid >> 5;
        int i = blockIdx.x * CHUNK + tid;
        int v = (tid < CHUNK && i < N_NODES) ? ((g_cnt[i] + 7) & ~7) : 0;
        int s = v;
        #pragma unroll
        for (int off = 1; off < 32; off <<= 1) {
            int n = __shfl_up_sync(0xffffffffu, s, off);
            if (lane >= off) s += n;
        }
        if (lane == 31) s_w[wid] = s;
        __syncthreads();
        if (wid == 0) {
            int ws = s_w[lane];
            #pragma unroll
            for (int off = 1; off < 32; off <<= 1) {
                int n = __shfl_up_sync(0xffffffffu, ws, off);
                if (lane >= off) ws += n;
            }
            s_w[lane] = ws;
        }
        __syncthreads();
        int woff = (wid > 0) ? s_w[wid - 1] : 0;
        if (tid < CHUNK && i < N_NODES) g_rowptr[i] = woff + s - v;
        if (tid == BUILD_THREADS - 1) g_bsum[blockIdx.x] = s_w[31];
    }
    grid_barrier();

    // --- phase 2b: block 0 scans the 148 block sums ---
    {
        __shared__ int sb[BUILD_BLOCKS];
        if (blockIdx.x == 0) {
            if (tid < BUILD_BLOCKS) sb[tid] = g_bsum[tid];
            __syncthreads();
            for (int off = 1; off < BUILD_BLOCKS; off <<= 1) {
                int t = (tid < BUILD_BLOCKS && tid >= off) ? sb[tid - off] : 0;
                __syncthreads();
                if (tid < BUILD_BLOCKS) sb[tid] += t;
                __syncthreads();
            }
            if (tid < BUILD_BLOCKS) g_boff[tid] = sb[tid] - g_bsum[tid];
            if (tid == BUILD_BLOCKS - 1) g_rowptr[N_NODES] = sb[BUILD_BLOCKS - 1];
        }
    }
    grid_barrier();

    // --- phase 2c: add block offsets; init cursors ---
    for (int i = gid; i < N_NODES; i += stride) {
        int r = g_rowptr[i] + g_boff[i / CHUNK];
        g_rowptr[i] = r;
        g_cursor[i] = r;
    }
    grid_barrier();

    // --- phase 3: place edges (payload: val, col*128 byte offset) ---
    for (int e = gid; e < N_EDGES; e += stride) {
        int r = load_idx(rptr, e, flag);
        int c = load_idx(cptr, e, flag);
        int pos = atomicAdd(&g_cursor[r], 1);
        g_edge[pos] = make_float2(vals[e], __int_as_float(c * (FPAD * 4)));
    }
}

// ---------------------------------------------------------------------------
// CSR SpMM, DEPTH-2 SOFTWARE PIPELINE (edges 2 ahead, gathers 1 ahead).
// One warp per row (the R14 structure -- best known); lanes in 4 groups of 8
// (g = lane>>3, q = lane&7). R15 showed the 40us wall is exposed gather
// latency: in-order issue makes FFMA(i) stall on gathers issued 2 instrs
// earlier, blocking the next iteration's loads. Fix: iteration i issues
//   edges(i+2)  [m]  -- independent
//   gathers(i+1)[h]  -- edge data arrived a full iteration ago
//   FFMA(i) on gathers issued a FULL ITERATION earlier [g]
// so the FFMA operand has ~1 loop body + warp-interleave of slack.
// Last-iteration gathers redirect to offset 0 (row 0, L1-hot) via 2 SELs
// instead of scatter-overreading. Edge prefetch overreads stay within
// EDGE_CAP slack and are never consumed.
// Per batch: 2x LDG.64 edges + 2x LDG.128 96B gathers (min(q,5)*16 skips
// the dead pad sector; lanes q=6,7 duplicate sector 2, structurally
// discarded by the fold) + 8 FFMA.
// __launch_bounds__(256, 6): pipeline needs ~40 regs; 75% occ is the
// explicit trade for hidden latency (R9's low-occ loss was WITHOUT hiding).
// Epilogue: butterfly fold (xor 8, xor 16); lanes 0-5 write one float4.
// ---------------------------------------------------------------------------
template <int DSTRIDE>
__global__ void __launch_bounds__(256, 6)
spmm_csr_kernel(const float* __restrict__ src, float* __restrict__ dst) {
    int w    = (blockIdx.x * blockDim.x + threadIdx.x) >> 5;  // row
    int lane = threadIdx.x & 31;

    int start = g_rowptr[w];          // multiple of 8
    int end   = g_rowptr[w + 1];      // padded end (pads contribute zero)

    int g = lane >> 3;                // edge-stream group 0..3
    int q = lane & 7;

    if (start == end) {               // empty row (astronomically rare)
        if (lane < 6)
            *(float4*)(dst + (size_t)w * DSTRIDE + lane * 4) =
                make_float4(0.f, 0.f, 0.f, 0.f);
        return;
    }

    const char* sp = (const char*)src + min(q, 5) * 16;  // bytes 0..95 only

    // Prologue: edges(0), edges(1) (overread ok), gathers(0).
    float2 e0 = g_edge[start + g];
    float2 e1 = g_edge[start + 4 + g];
    float2 f0 = g_edge[start + 8 + g];
    float2 f1 = g_edge[start + 12 + g];
    float4 g0 = *(const float4*)(sp + __float_as_int(e0.y));
    float4 g1 = *(const float4*)(sp + __float_as_int(e1.y));

    float4 acc = make_float4(0.f, 0.f, 0.f, 0.f);

    for (int e = start; e < end; e += 8) {
        // edges(i+2) -- independent prefetch (overread within EDGE_CAP slack)
        float2 m0 = g_edge[e + 16 + g];
        float2 m1 = g_edge[e + 20 + g];
        // gathers(i+1) -- edge data (f0,f1) arrived a full iteration ago.
        // Beyond the row, redirect to offset 0 (row 0 line, L1-hot).
        bool more = (e + 8) < end;
        int o0 = more ? __float_as_int(f0.y) : 0;
        int o1 = more ? __float_as_int(f1.y) : 0;
        float4 h0 = *(const float4*)(sp + o0);
        float4 h1 = *(const float4*)(sp + o1);
        // FFMA(i): gathers g0,g1 were issued one full iteration ago.
        acc.x = fmaf(e0.x, g0.x, acc.x);
        acc.y = fmaf(e0.x, g0.y, acc.y);
        acc.z = fmaf(e0.x, g0.z, acc.z);
        acc.w = fmaf(e0.x, g0.w, acc.w);
        acc.x = fmaf(e1.x, g1.x, acc.x);
        acc.y = fmaf(e1.x, g1.y, acc.y);
        acc.z = fmaf(e1.x, g1.z, acc.z);
        acc.w = fmaf(e1.x, g1.w, acc.w);
        // rotate pipeline state
        e0 = f0; e1 = f1;
        f0 = m0; f1 = m1;
        g0 = h0; g1 = h1;
    }

    // Fold the 4 edge-stream groups: lanes {q, q+8, q+16, q+24} -> lane q.
    acc.x += __shfl_xor_sync(0xffffffffu, acc.x, 8);
    acc.y += __shfl_xor_sync(0xffffffffu, acc.y, 8);
    acc.z += __shfl_xor_sync(0xffffffffu, acc.z, 8);
    acc.w += __shfl_xor_sync(0xffffffffu, acc.w, 8);
    acc.x += __shfl_xor_sync(0xffffffffu, acc.x, 16);
    acc.y += __shfl_xor_sync(0xffffffffu, acc.y, 16);
    acc.z += __shfl_xor_sync(0xffffffffu, acc.z, 16);
    acc.w += __shfl_xor_sync(0xffffffffu, acc.w, 16);

    if (lane < 6)   // lanes 0-5 cover feats 0..23 (float4 each)
        *(float4*)(dst + (size_t)w * DSTRIDE + lane * 4) = acc;
}

// ---------------------------------------------------------------------------
// kernel_launch: one build launch, then 6 SpMMs. x copied into padded bufP
// inside build; chain P->Q->P->Q->P->Q->out (final instantiation writes at
// stride 24). Default stream, no syncs, no allocations -> graph-capturable.
// ---------------------------------------------------------------------------
extern "C" void kernel_launch(void* const* d_in, const int* in_sizes, int n_in,
                              void* d_out, int out_size) {
    const float* x    = (const float*)d_in[0];  // [N_NODES, N_FEAT]
    const float* vals = (const float*)d_in[1];  // [N_EDGES]
    const void*  rraw = d_in[2];                // [N_EDGES] int32 or int64
    const void*  craw = d_in[3];                // [N_EDGES] int32 or int64
    float* out = (float*)d_out;                 // [N_NODES, N_FEAT]

    float* bufP;
    float* bufQ;
    cudaGetSymbolAddress((void**)&bufP, g_bufP);
    cudaGetSymbolAddress((void**)&bufQ, g_bufQ);

    const int sblocks = N_NODES / 8;   // 12500 blocks, warp per row

    build_csr_kernel<<<BUILD_BLOCKS, BUILD_THREADS>>>(rraw, craw, vals, x);

    // Layers 1-5 into padded buffers, final layer into d_out (stride 24).
    spmm_csr_kernel<FPAD><<<sblocks, 256>>>(bufP, bufQ);
    spmm_csr_kernel<FPAD><<<sblocks, 256>>>(bufQ, bufP);
    spmm_csr_kernel<FPAD><<<sblocks, 256>>>(bufP, bufQ);
    spmm_csr_kernel<FPAD><<<sblocks, 256>>>(bufQ, bufP);
    spmm_csr_kernel<FPAD><<<sblocks, 256>>>(bufP, bufQ);
    spmm_csr_kernel<N_FEAT><<<sblocks, 256>>>(bufQ, out);
}

// round 17
// speedup vs baseline: 1.2404x; 1.2404x over previous
#include <cuda_runtime.h>
#include <cstdint>

#define N_NODES 100000
#define N_EDGES 3200000
#define N_FEAT  24
#define FPAD    32                 // padded feature stride (128 bytes)
#define LAYERS  6
#define EDGE_CAP 4000000           // padded total <= E + 7N = 3.9M; slack covers prefetch overread
#define BUILD_BLOCKS  148
#define BUILD_THREADS 1024
#define CHUNK 676                  // ceil(N_NODES / BUILD_BLOCKS)

#define SPMM_BLOCKS 1184           // 148 SMs x 8 blocks = one wave
#define SPMM_WARPS  (SPMM_BLOCKS * 8)   // 9472; warp k owns rows k, k+9472, ...

// ---------------------------------------------------------------------------
// Scratch (allocation-free rule: __device__ globals).
// Padded CSR: each row's g_edge segment is padded to a multiple of 8. Pad
// slots are NEVER written; __device__ globals are zero-init, so pads are
// permanently (val=0, off=0) -> harmless gathers of row 0 scaled by 0.
// Deterministic layout -> replay-safe. Feature buffers padded to FPAD=32
// floats (128B); only bytes 0..95 of a row are ever requested.
// ---------------------------------------------------------------------------
__device__ __align__(16) float  g_bufP[(size_t)N_NODES * FPAD];
__device__ __align__(16) float  g_bufQ[(size_t)N_NODES * FPAD];
__device__ __align__(16) float2 g_edge[EDGE_CAP];   // (val, col*128 bits)
__device__ int g_cnt[N_NODES];        // real row lengths (build only)
__device__ int g_rowptr[N_NODES + 1]; // PADDED exclusive prefix
__device__ int g_cursor[N_NODES];
__device__ int g_bsum[BUILD_BLOCKS];
// Monotone: int32 inputs -> set to 1 every run (idempotent); int64 -> stays 0.
__device__ int g_flag = 0;
// Monotone ticket barrier counter; never reset -> replay-safe.
__device__ unsigned g_bar = 0;

// ---------------------------------------------------------------------------
// Software grid barrier (persistent build kernel; 148 blocks = wave 1).
// Uniform across blocks: every block executes the same barrier sequence
// (the only conditional path keys off g_flag, which is globally uniform
// after the first barrier).
// ---------------------------------------------------------------------------
__device__ __forceinline__ void grid_barrier() {
    __syncthreads();
    if (threadIdx.x == 0) {
        __threadfence();
        unsigned ticket = atomicAdd(&g_bar, 1u);
        unsigned target = (ticket / BUILD_BLOCKS + 1u) * BUILD_BLOCKS;
        unsigned v;
        do {
            asm volatile("ld.global.acquire.gpu.u32 %0, [%1];"
                         : "=r"(v) : "l"(&g_bar));
            if (v < target) __nanosleep(64);
        } while (v < target);
    }
    __syncthreads();
}

__device__ __forceinline__ int load_idx(const void* p, int e, int flag) {
    int v = (flag == 1) ? ((const int*)p)[e] : (int)((const long long*)p)[e];
    return min(max(v, 0), N_NODES - 1);   // fault guard
}

// ---------------------------------------------------------------------------
// Persistent single-launch CSR build + x copy-in:
//   phase 0: zero counts, copy x -> bufP, SAMPLED dtype probe (64 odd words
//            by block 0: JAX x64-off downcasts int64->int32; for int64 the
//            odd words are all zero, for int32 they are random indices --
//            P(64 samples all zero | int32) ~ 1e-320)
//   phase 1: row histogram
//   phase 2a: block-local exclusive scan of counts padded to multiples of 8
//   phase 2c: each block sums prior block totals itself (merged old 2b) and
//             adds the offset to its own chunk; init cursors
//   phase 3: scatter (val, col*128) into row-sorted padded g_edge
// ---------------------------------------------------------------------------
__global__ void __launch_bounds__(BUILD_THREADS)
build_csr_kernel(const void* __restrict__ rptr,
                 const void* __restrict__ cptr,
                 const float* __restrict__ vals,
                 const float* __restrict__ x) {
    const int tid    = threadIdx.x;
    const int gid    = blockIdx.x * BUILD_THREADS + tid;
    const int stride = BUILD_BLOCKS * BUILD_THREADS;

    // --- phase 0 ---
    for (int i = gid; i < N_NODES; i += stride) g_cnt[i] = 0;
    if (blockIdx.x == 0 && tid < 64) {
        const int* p32 = (const int*)rptr;
        int w = (tid * 50021 + 997) % (N_EDGES / 2);
        if (p32[2 * w + 1] != 0) g_flag = 1;
    }
    for (int i = gid; i < N_NODES * N_FEAT; i += stride) {
        int r = i / N_FEAT, f = i - r * N_FEAT;
        g_bufP[r * FPAD + f] = x[i];
    }
    grid_barrier();

    const int flag = g_flag;

    // --- phase 1: histogram ---
    for (int e = gid; e < N_EDGES; e += stride)
        atomicAdd(&g_cnt[load_idx(rptr, e, flag)], 1);
    grid_barrier();

    // --- phase 2a: block-local exclusive scan of padded counts ---
    {
        __shared__ int s_w[32];
        int lane = tid & 31, wid = tid >> 5;
        int i = blockIdx.x * CHUNK + tid;
        int v = (tid < CHUNK && i < N_NODES) ? ((g_cnt[i] + 7) & ~7) : 0;
        int s = v;
        #pragma unroll
        for (int off = 1; off < 32; off <<= 1) {
            int n = __shfl_up_sync(0xffffffffu, s, off);
            if (lane >= off) s += n;
        }
        if (lane == 31) s_w[wid] = s;
        __syncthreads();
        if (wid == 0) {
            int ws = s_w[lane];
            #pragma unroll
            for (int off = 1; off < 32; off <<= 1) {
                int n = __shfl_up_sync(0xffffffffu, ws, off);
                if (lane >= off) ws += n;
            }
            s_w[lane] = ws;
        }
        __syncthreads();
        int woff = (wid > 0) ? s_w[wid - 1] : 0;
        if (tid < CHUNK && i < N_NODES) g_rowptr[i] = woff + s - v;
        if (tid == BUILD_THREADS - 1) g_bsum[blockIdx.x] = s_w[31];
    }
    grid_barrier();

    // --- phase 2c (merged 2b): each block computes its own offset from the
    //     148 block sums, then adds it to its chunk; init cursors. ---
    {
        __shared__ int sb[BUILD_BLOCKS];
        __shared__ int s_boff;
        if (tid < BUILD_BLOCKS) sb[tid] = g_bsum[tid];
        __syncthreads();
        if (tid == 0) {
            int acc = 0;
            for (int j = 0; j < (int)blockIdx.x; j++) acc += sb[j];
            s_boff = acc;
            if (blockIdx.x == BUILD_BLOCKS - 1)
                g_rowptr[N_NODES] = acc + sb[BUILD_BLOCKS - 1];
        }
        __syncthreads();
        int i = blockIdx.x * CHUNK + tid;
        if (tid < CHUNK && i < N_NODES) {
            int r = g_rowptr[i] + s_boff;
            g_rowptr[i] = r;
            g_cursor[i] = r;
        }
    }
    grid_barrier();

    // --- phase 3: place edges (payload: val, col*128 byte offset) ---
    for (int e = gid; e < N_EDGES; e += stride) {
        int r = load_idx(rptr, e, flag);
        int c = load_idx(cptr, e, flag);
        int pos = atomicAdd(&g_cursor[r], 1);
        g_edge[pos] = make_float2(vals[e], __int_as_float(c * (FPAD * 4)));
    }
}

// ---------------------------------------------------------------------------
// CSR SpMM: the R14 single-row body (best known: per-group edge loads,
// single-step edge prefetch, 96B sector-trimmed gathers, butterfly fold),
// wrapped in a STRIDED MULTI-ROW loop for load balance. Warp k processes
// rows k, k+9472, ... (~10.5 rows): per-warp work = sum of ~10.5 Poisson(32)
// rows (sigma ~6%) instead of a single row (sigma ~40%), so the 8 warps of
// a block finish together and block registers are not held hostage by one
// long row -- recovering the ~17% occupancy lost to intra-block tails that
// held R12-R16 at ~40us/layer. Grid = 1184 blocks = 8/SM, exactly one wave.
// Per 8-edge batch: 2x LDG.64 edges (4 group addresses span 32 aligned
// bytes: one wavefront, zero selects) + 2x LDG.128 96B gathers
// (min(q,5)*16 skips the dead pad sector; lanes q=6,7 duplicate sector 2
// and are structurally discarded by the fold) + 8 FFMA.
// __launch_bounds__(256, 8) pins regs <= 32 -> 8 blocks/SM.
// ---------------------------------------------------------------------------
template <int DSTRIDE>
__global__ void __launch_bounds__(256, 8)
spmm_csr_kernel(const float* __restrict__ src, float* __restrict__ dst) {
    int wid  = (blockIdx.x * blockDim.x + threadIdx.x) >> 5;  // 0..9471
    int lane = threadIdx.x & 31;

    int g = lane >> 3;                // edge-stream group 0..3
    int q = lane & 7;
    const char* sp = (const char*)src + min(q, 5) * 16;  // bytes 0..95 only

    for (int w = wid; w < N_NODES; w += SPMM_WARPS) {
        int start = g_rowptr[w];      // multiple of 8
        int end   = g_rowptr[w + 1];  // padded end (pads contribute zero)

        float4 acc = make_float4(0.f, 0.f, 0.f, 0.f);

        if (start < end) {
            // Prologue: batch 0's edges.
            float2 e0 = g_edge[start + g];
            float2 e1 = g_edge[start + 4 + g];

            for (int e = start; e < end; e += 8) {
                // Prefetch next batch's edges first (independent; overread
                // stays within EDGE_CAP slack and is never consumed).
                float2 n0 = g_edge[e + 8 + g];
                float2 n1 = g_edge[e + 12 + g];
                float4 g0 = *(const float4*)(sp + __float_as_int(e0.y));
                float4 g1 = *(const float4*)(sp + __float_as_int(e1.y));
                acc.x = fmaf(e0.x, g0.x, acc.x);
                acc.y = fmaf(e0.x, g0.y, acc.y);
                acc.z = fmaf(e0.x, g0.z, acc.z);
                acc.w = fmaf(e0.x, g0.w, acc.w);
                acc.x = fmaf(e1.x, g1.x, acc.x);
                acc.y = fmaf(e1.x, g1.y, acc.y);
                acc.z = fmaf(e1.x, g1.z, acc.z);
                acc.w = fmaf(e1.x, g1.w, acc.w);
                e0 = n0;
                e1 = n1;
            }

            // Fold the 4 groups: lanes {q, q+8, q+16, q+24} -> lane q.
            acc.x += __shfl_xor_sync(0xffffffffu, acc.x, 8);
            acc.y += __shfl_xor_sync(0xffffffffu, acc.y, 8);
            acc.z += __shfl_xor_sync(0xffffffffu, acc.z, 8);
            acc.w += __shfl_xor_sync(0xffffffffu, acc.w, 8);
            acc.x += __shfl_xor_sync(0xffffffffu, acc.x, 16);
            acc.y += __shfl_xor_sync(0xffffffffu, acc.y, 16);
            acc.z += __shfl_xor_sync(0xffffffffu, acc.z, 16);
            acc.w += __shfl_xor_sync(0xffffffffu, acc.w, 16);
        }

        if (lane < 6)   // lanes 0-5 cover feats 0..23 (float4 each)
            *(float4*)(dst + (size_t)w * DSTRIDE + lane * 4) = acc;
    }
}

// ---------------------------------------------------------------------------
// kernel_launch: one build launch, then 6 SpMMs. x copied into padded bufP
// inside build; chain P->Q->P->Q->P->Q->out (final instantiation writes at
// stride 24). Default stream, no syncs, no allocations -> graph-capturable.
// ---------------------------------------------------------------------------
extern "C" void kernel_launch(void* const* d_in, const int* in_sizes, int n_in,
                              void* d_out, int out_size) {
    const float* x    = (const float*)d_in[0];  // [N_NODES, N_FEAT]
    const float* vals = (const float*)d_in[1];  // [N_EDGES]
    const void*  rraw = d_in[2];                // [N_EDGES] int32 or int64
    const void*  craw = d_in[3];                // [N_EDGES] int32 or int64
    float* out = (float*)d_out;                 // [N_NODES, N_FEAT]

    float* bufP;
    float* bufQ;
    cudaGetSymbolAddress((void**)&bufP, g_bufP);
    cudaGetSymbolAddress((void**)&bufQ, g_bufQ);

    build_csr_kernel<<<BUILD_BLOCKS, BUILD_THREADS>>>(rraw, craw, vals, x);

    // Layers 1-5 into padded buffers, final layer into d_out (stride 24).
    spmm_csr_kernel<FPAD><<<SPMM_BLOCKS, 256>>>(bufP, bufQ);
    spmm_csr_kernel<FPAD><<<SPMM_BLOCKS, 256>>>(bufQ, bufP);
    spmm_csr_kernel<FPAD><<<SPMM_BLOCKS, 256>>>(bufP, bufQ);
    spmm_csr_kernel<FPAD><<<SPMM_BLOCKS, 256>>>(bufQ, bufP);
    spmm_csr_kernel<FPAD><<<SPMM_BLOCKS, 256>>>(bufP, bufQ);
    spmm_csr_kernel<N_FEAT><<<SPMM_BLOCKS, 256>>>(bufQ, out);
}